// round 5
// baseline (speedup 1.0000x reference)
#include <cuda_runtime.h>

// ---------------------------------------------------------------------------
// BLSTM_NMC: Bayesian LSTM, B=512, S=128, H=512, IN=1, OUT=1.
//   W = mu + softplus(rho)*eps  (ih, hh, bias)
//   xm[b,s] = x[b,s] * mask_in[b,s]        (IN==1, so x_proj is rank-1)
//   128 recurrent steps: gates = xm[t]*W_ih + bias + h @ W_hh ; LSTM cell
//   out[b] = sum_j h_last[b,j]*mask_out[b,j]*W_lin[j] + b_lin[0]
//
// Step kernel: fused GEMM (M=512, fused-N = 512 hidden x 4 gates, K=512)
//   + LSTM cell. 128 CTAs x 128 threads; CTA tile 64(batch) x 128(fused cols
//   = 32 hidden cols x 4 gates); thread tile 8x8; packed fma.rn.f32x2 inner
//   loop (FFMA2, full 128 FMA/cyc/SM rate); double-buffered SMEM; h double-
//   buffered in global. Gates recombined through SMEM (reusing the GEMM
//   buffers) so the cell update never touches global gates.
// ---------------------------------------------------------------------------

#define BB 512
#define SS 128
#define HH 512
#define G4 2048

#define TM 64
#define TN 128
#define KB 16
#define NCH (HH / KB)      // 32 k-chunks
#define NTHREADS 128

#define AS_STRIDE 68       // 64 + pad
#define BS_STRIDE 132      // 128 + pad
#define A_BUF (KB * AS_STRIDE)   // 1088 floats
#define B_BUF (KB * BS_STRIDE)   // 2112 floats
// pool must hold max(2*A_BUF + 2*B_BUF = 6400, Sg = 64*132 = 8448)
#define POOL_FLOATS 8448

// ---------------- scratch (device globals; no allocation allowed) ----------
__device__ float g_Whh[HH * G4];       // sampled W_hh, [k][n] row-major (4 MB)
__device__ float g_bias[G4];
__device__ float g_Wih[G4];
__device__ float g_xm[SS * BB];        // transposed: xm[s*B + b]
__device__ float g_h[2][BB * HH];      // double-buffered hidden state
__device__ float g_c[BB * HH];         // cell state (in-place per element)

// ---------------- helpers --------------------------------------------------
static __device__ __forceinline__ float softplus_f(float x) {
    return (x > 20.0f) ? x : log1pf(expf(x));
}
static __device__ __forceinline__ float sigm(float x) {
    // |x| large: expf(-x) -> inf or 0, both give correct limits
    return __fdividef(1.0f, 1.0f + __expf(-x));
}
static __device__ __forceinline__ float tanh_fast(float x) {
    // overflow-safe: e can be +inf (c may grow over 128 steps) -> r = 1
    float e = __expf(2.0f * fabsf(x));
    float r = 1.0f - __fdividef(2.0f, e + 1.0f);
    return copysignf(r, x);
}

static __device__ __forceinline__ unsigned long long pk2(float lo, float hi) {
    unsigned long long r;
    asm("mov.b64 %0, {%1, %2};" : "=l"(r) : "f"(lo), "f"(hi));
    return r;
}
static __device__ __forceinline__ void fma2(unsigned long long& d,
                                            unsigned long long a,
                                            unsigned long long b) {
    asm("fma.rn.f32x2 %0, %1, %2, %0;" : "+l"(d) : "l"(a), "l"(b));
}
static __device__ __forceinline__ void upk2(unsigned long long v, float& lo, float& hi) {
    asm("mov.b64 {%0, %1}, %2;" : "=f"(lo), "=f"(hi) : "l"(v));
}

// ---------------- setup kernels --------------------------------------------
__global__ void k_init(const float* __restrict__ x, const float* __restrict__ mask_in,
                       const float* __restrict__ Wih_mu, const float* __restrict__ Wih_rho,
                       const float* __restrict__ eps_ih,
                       const float* __restrict__ b_mu, const float* __restrict__ b_rho,
                       const float* __restrict__ eps_b) {
    int idx = blockIdx.x * blockDim.x + threadIdx.x;
    if (idx < BB * HH) {
        g_h[0][idx] = 0.0f;
        g_c[idx] = 0.0f;
    }
    if (idx < BB * SS) {
        int b = idx >> 7;          // x is (B,S) row-major
        int s = idx & (SS - 1);
        g_xm[s * BB + b] = x[idx] * mask_in[idx];   // mask_in is (B,S,1)
    }
    if (idx < G4) {
        g_Wih[idx]  = Wih_mu[idx] + softplus_f(Wih_rho[idx]) * eps_ih[idx];
        g_bias[idx] = b_mu[idx]   + softplus_f(b_rho[idx])   * eps_b[idx];
    }
}

__global__ void k_sample_whh(const float* __restrict__ mu, const float* __restrict__ rho,
                             const float* __restrict__ eps) {
    int idx = blockIdx.x * blockDim.x + threadIdx.x;
    if (idx < HH * G4)
        g_Whh[idx] = mu[idx] + softplus_f(rho[idx]) * eps[idx];
}

// ---------------- recurrent step kernel ------------------------------------
__global__ __launch_bounds__(NTHREADS, 1)
void k_step(int t) {
    __shared__ __align__(16) float pool[POOL_FLOATS];
    float* As = pool;                    // [2][KB][AS_STRIDE]  layout [k][m]
    float* Bs = pool + 2 * A_BUF;        // [2][KB][BS_STRIDE]  layout [k][n]

    const int tid = threadIdx.x;
    const int bx  = blockIdx.x;          // 0..127
    const int bm0 = (bx >> 4) * TM;      // batch tile origin (8 tiles)
    const int hc0 = (bx & 15) * 32;      // hidden-col tile origin (16 tiles)

    const float* __restrict__ hin = g_h[t & 1];

    // A (h) global->smem mapping: thread loads 2 float4 per chunk (rows r, r+32)
    const int aq = tid & 3;              // k-quad within chunk
    const int ar = tid >> 2;             // row 0..31
    // B (W_hh) mapping: thread loads 4 float4 per chunk (k = bkr + 4*i)
    const int bn4 = tid & 31;            // float4 slot in fused-N (0..31)
    const int bkr = tid >> 5;            // 0..3
    const int bcol = ((bn4 >> 3) << 9) + hc0 + ((bn4 & 7) << 2); // gate*512 + hc0 + j

    const int tm8 = (tid >> 4) << 3;     // 8 rows owned
    const int tn8 = (tid & 15) << 3;     // 8 fused cols owned

    unsigned long long acc[8][4];
#pragma unroll
    for (int i = 0; i < 8; i++)
#pragma unroll
        for (int j = 0; j < 4; j++) acc[i][j] = 0ull;

    float4 ra0, ra1, rb0, rb1, rb2, rb3;

    // ---- load chunk 0
    {
        const int k0 = 0;
        ra0 = *(const float4*)&hin[(bm0 + ar) * HH + k0 + aq * 4];
        ra1 = *(const float4*)&hin[(bm0 + ar + 32) * HH + k0 + aq * 4];
        rb0 = *(const float4*)&g_Whh[(k0 + bkr) * G4 + bcol];
        rb1 = *(const float4*)&g_Whh[(k0 + bkr + 4) * G4 + bcol];
        rb2 = *(const float4*)&g_Whh[(k0 + bkr + 8) * G4 + bcol];
        rb3 = *(const float4*)&g_Whh[(k0 + bkr + 12) * G4 + bcol];
    }

#define STS_CHUNK(BUFI)                                                          \
    do {                                                                         \
        float* Ab = As + (BUFI) * A_BUF;                                         \
        float* Bb = Bs + (BUFI) * B_BUF;                                         \
        Ab[(aq * 4 + 0) * AS_STRIDE + ar] = ra0.x;                               \
        Ab[(aq * 4 + 1) * AS_STRIDE + ar] = ra0.y;                               \
        Ab[(aq * 4 + 2) * AS_STRIDE + ar] = ra0.z;                               \
        Ab[(aq * 4 + 3) * AS_STRIDE + ar] = ra0.w;                               \
        Ab[(aq * 4 + 0) * AS_STRIDE + ar + 32] = ra1.x;                          \
        Ab[(aq * 4 + 1) * AS_STRIDE + ar + 32] = ra1.y;                          \
        Ab[(aq * 4 + 2) * AS_STRIDE + ar + 32] = ra1.z;                          \
        Ab[(aq * 4 + 3) * AS_STRIDE + ar + 32] = ra1.w;                          \
        *(float4*)&Bb[(bkr) * BS_STRIDE + bn4 * 4] = rb0;                        \
        *(float4*)&Bb[(bkr + 4) * BS_STRIDE + bn4 * 4] = rb1;                    \
        *(float4*)&Bb[(bkr + 8) * BS_STRIDE + bn4 * 4] = rb2;                    \
        *(float4*)&Bb[(bkr + 12) * BS_STRIDE + bn4 * 4] = rb3;                   \
    } while (0)

    STS_CHUNK(0);
    __syncthreads();

    for (int ch = 0; ch < NCH; ch++) {
        const int cur = ch & 1;
        if (ch + 1 < NCH) {   // prefetch next chunk into registers
            const int k0 = (ch + 1) * KB;
            ra0 = *(const float4*)&hin[(bm0 + ar) * HH + k0 + aq * 4];
            ra1 = *(const float4*)&hin[(bm0 + ar + 32) * HH + k0 + aq * 4];
            rb0 = *(const float4*)&g_Whh[(k0 + bkr) * G4 + bcol];
            rb1 = *(const float4*)&g_Whh[(k0 + bkr + 4) * G4 + bcol];
            rb2 = *(const float4*)&g_Whh[(k0 + bkr + 8) * G4 + bcol];
            rb3 = *(const float4*)&g_Whh[(k0 + bkr + 12) * G4 + bcol];
        }
        const float* Ab = As + cur * A_BUF;
        const float* Bb = Bs + cur * B_BUF;
#pragma unroll
        for (int kk = 0; kk < KB; kk++) {
            float4 av0 = *(const float4*)&Ab[kk * AS_STRIDE + tm8];
            float4 av1 = *(const float4*)&Ab[kk * AS_STRIDE + tm8 + 4];
            float4 bv0 = *(const float4*)&Bb[kk * BS_STRIDE + tn8];
            float4 bv1 = *(const float4*)&Bb[kk * BS_STRIDE + tn8 + 4];
            unsigned long long bp0 = pk2(bv0.x, bv0.y);
            unsigned long long bp1 = pk2(bv0.z, bv0.w);
            unsigned long long bp2 = pk2(bv1.x, bv1.y);
            unsigned long long bp3 = pk2(bv1.z, bv1.w);
            float a[8] = {av0.x, av0.y, av0.z, av0.w, av1.x, av1.y, av1.z, av1.w};
#pragma unroll
            for (int i = 0; i < 8; i++) {
                unsigned long long ap = pk2(a[i], a[i]);
                fma2(acc[i][0], ap, bp0);
                fma2(acc[i][1], ap, bp1);
                fma2(acc[i][2], ap, bp2);
                fma2(acc[i][3], ap, bp3);
            }
        }
        if (ch + 1 < NCH) {
            STS_CHUNK(cur ^ 1);
            __syncthreads();
        }
    }

    // ---- epilogue: add input projection + bias, recombine gates via SMEM
    __syncthreads();                       // done reading As/Bs; reuse pool as Sg
    float* Sg = pool;                      // [TM][BS_STRIDE]

    // the 8 fused cols of this thread are within one gate block (8 | 32)
    const int cbase = ((tn8 >> 5) << 9) + hc0 + (tn8 & 31);
    float gw[8], gb[8];
#pragma unroll
    for (int j = 0; j < 8; j++) {
        gw[j] = g_Wih[cbase + j];
        gb[j] = g_bias[cbase + j];
    }
    const float* __restrict__ xmrow = g_xm + t * BB + bm0;
#pragma unroll
    for (int i = 0; i < 8; i++) {
        float xv = xmrow[tm8 + i];
#pragma unroll
        for (int j = 0; j < 4; j++) {
            float lo, hi;
            upk2(acc[i][j], lo, hi);
            int n0 = tn8 + j * 2;   // local fused col (relative to this thread's gate run)
            int jj = n0 - tn8;
            Sg[(tm8 + i) * BS_STRIDE + n0]     = lo + xv * gw[jj]     + gb[jj];
            Sg[(tm8 + i) * BS_STRIDE + n0 + 1] = hi + xv * gw[jj + 1] + gb[jj + 1];
        }
    }
    __syncthreads();

    // ---- LSTM cell: 64 rows x 32 hidden cols per CTA
    float* __restrict__ hout = g_h[(t + 1) & 1];
#pragma unroll
    for (int e = tid; e < TM * 32; e += NTHREADS) {
        int bl = e >> 5;
        int jh = e & 31;
        float ig = Sg[bl * BS_STRIDE + jh];
        float fg = Sg[bl * BS_STRIDE + 32 + jh];
        float gg = Sg[bl * BS_STRIDE + 64 + jh];
        float og = Sg[bl * BS_STRIDE + 96 + jh];
        int idx = (bm0 + bl) * HH + hc0 + jh;
        float c  = g_c[idx];
        float it = sigm(ig);
        float ft = sigm(fg);
        float gt = tanh_fast(gg);
        float ot = sigm(og);
        float cn = ft * c + it * gt;
        g_c[idx]  = cn;
        hout[idx] = ot * tanh_fast(cn);
    }
#undef STS_CHUNK
}

// ---------------- output head ----------------------------------------------
__global__ void k_final(const float* __restrict__ W_lin, const float* __restrict__ b_lin,
                        const float* __restrict__ mask_out, float* __restrict__ out) {
    int b = blockIdx.x;
    int tid = threadIdx.x;
    const float* hrow = g_h[0] + b * HH;   // after 128 steps h_last is in buf 0
    const float* mrow = mask_out + b * HH;
    float s = 0.0f;
    for (int j = tid; j < HH; j += 128)
        s += hrow[j] * mrow[j] * W_lin[j];
    __shared__ float red[128];
    red[tid] = s;
    __syncthreads();
    for (int off = 64; off > 0; off >>= 1) {
        if (tid < off) red[tid] += red[tid + off];
        __syncthreads();
    }
    if (tid == 0) out[b] = red[0] + b_lin[0];
}

// ---------------- launch ----------------------------------------------------
extern "C" void kernel_launch(void* const* d_in, const int* in_sizes, int n_in,
                              void* d_out, int out_size) {
    const float* x        = (const float*)d_in[0];
    const float* Wih_mu   = (const float*)d_in[1];
    const float* Wih_rho  = (const float*)d_in[2];
    const float* eps_ih   = (const float*)d_in[3];
    const float* Whh_mu   = (const float*)d_in[4];
    const float* Whh_rho  = (const float*)d_in[5];
    const float* eps_hh   = (const float*)d_in[6];
    const float* b_mu     = (const float*)d_in[7];
    const float* b_rho    = (const float*)d_in[8];
    const float* eps_b    = (const float*)d_in[9];
    const float* W_lin    = (const float*)d_in[10];
    const float* b_lin    = (const float*)d_in[11];
    const float* mask_in  = (const float*)d_in[12];
    const float* mask_out = (const float*)d_in[13];
    float* out = (float*)d_out;
    (void)in_sizes; (void)n_in; (void)out_size;

    k_init<<<(BB * HH + 255) / 256, 256>>>(x, mask_in, Wih_mu, Wih_rho, eps_ih,
                                           b_mu, b_rho, eps_b);
    k_sample_whh<<<(HH * G4 + 255) / 256, 256>>>(Whh_mu, Whh_rho, eps_hh);
    for (int t = 0; t < SS; t++)
        k_step<<<128, NTHREADS>>>(t);
    k_final<<<BB, 128>>>(W_lin, b_lin, mask_out, out);
}